// round 1
// baseline (speedup 1.0000x reference)
#include <cuda_runtime.h>
#include <cuda_fp16.h>

#define BB 64
#define TT 1024
#define II 128
#define HH 512

static constexpr int   NCTA2 = 64;   // phase-2 CTAs (1 per SM, co-resident)
static constexpr int   THR2  = 128;  // 4 warps
static constexpr float DT_C  = 0.1f;
static constexpr float EPS_C = 1e-8f;

// ---------------- scratch (device globals: no allocation allowed) ----------------
__device__ __align__(16) __half g_xh  [BB * TT * II];   // x in fp16          (16.8 MB)
__device__ __align__(16) __half g_w1  [4 * HH * II];    // [mat][j][k] fp16   (Wsw,Wsm,Wss,Wtcx)
__device__ __align__(16) __half g_w2  [4 * HH * HH];    // [mat][j][k] fp16   (Wtch,Wiw,Wim,Wis)
__device__ __align__(16) __half g_sens[TT * BB * HH];   // sensory, (t,b,j)   (64 MB)
__device__ __align__(16) __half g_tcx [TT * BB * HH];   // tcx+btc, (t,b,j)   (64 MB)
__device__ __align__(16) __half g_hbuf[2 * BB * HH];    // ping-pong h (fp16 broadcast copy)
__device__ unsigned          g_bar;
__device__ volatile unsigned g_gen;

// ---------------- mma.sync m16n8k16 f16 -> f32 ----------------
__device__ __forceinline__ void mma16816(float* c,
                                         unsigned a0, unsigned a1, unsigned a2, unsigned a3,
                                         unsigned b0, unsigned b1) {
    asm volatile(
        "mma.sync.aligned.m16n8k16.row.col.f32.f16.f16.f32 "
        "{%0,%1,%2,%3},{%4,%5,%6,%7},{%8,%9},{%0,%1,%2,%3};\n"
        : "+f"(c[0]), "+f"(c[1]), "+f"(c[2]), "+f"(c[3])
        : "r"(a0), "r"(a1), "r"(a2), "r"(a3), "r"(b0), "r"(b1));
}

// ---------------- prep: fp16 conversion, weight packing, state init ----------------
__global__ void prep_kernel(const float* __restrict__ x,
                            const float* __restrict__ Wsw, const float* __restrict__ Wsm,
                            const float* __restrict__ Wss, const float* __restrict__ Wtcx,
                            const float* __restrict__ Wtch, const float* __restrict__ Wiw,
                            const float* __restrict__ Wim, const float* __restrict__ Wis) {
    long long i = (long long)blockIdx.x * blockDim.x + threadIdx.x;
    if (i < (long long)BB * TT * II) g_xh[i] = __float2half(x[i]);
    if (i < 4 * HH * II) {
        int mat = (int)(i / (HH * II)); int rem = (int)(i % (HH * II));
        const float* W = (mat == 0) ? Wsw : (mat == 1) ? Wsm : (mat == 2) ? Wss : Wtcx;
        g_w1[i] = __float2half(W[rem]);
    }
    if (i < 4 * HH * HH) {
        int mat = (int)(i / (HH * HH)); int rem = (int)(i % (HH * HH));
        const float* W = (mat == 0) ? Wtch : (mat == 1) ? Wiw : (mat == 2) ? Wim : Wis;
        g_w2[i] = __float2half(W[rem]);
    }
    if (i < BB * HH) g_hbuf[i] = __float2half(1.0f);   // h0 = ones, buffer 0
    if (i == 0) { g_bar = 0; g_gen = 0; }
}

// ---------------- phase 1: input projections -> sensory & tcx ----------------
// GEMM: (B*T, I) x (I, 4H), CTA tile = 128 rows x 32 hidden units (x 4 mats = 128 cols)
#define P1_PITCH 136   // 128 + 8 halves pad (conflict-free)
struct P1Smem {
    __half A[128 * P1_PITCH];
    __half W[128 * P1_PITCH];
    __half sens[128 * 32];
    __half tcx[128 * 32];
};

__global__ void phase1_kernel(const float* __restrict__ bsw, const float* __restrict__ bsm,
                              const float* __restrict__ bss, const float* __restrict__ btc) {
    extern __shared__ char smem_raw[];
    P1Smem& S = *reinterpret_cast<P1Smem*>(smem_raw);
    const int tid = threadIdx.x;
    const int m0 = blockIdx.x * 128;
    const int j0 = blockIdx.y * 32;

    // load x tile (128 x 128 halves)
    {
        const uint4* src = reinterpret_cast<const uint4*>(g_xh + (size_t)m0 * II);
        for (int i = tid; i < 128 * 16; i += 256) {
            int r = i >> 4, c = i & 15;
            *reinterpret_cast<uint4*>(&S.A[r * P1_PITCH + c * 8]) = src[r * 16 + c];
        }
    }
    // load weight tile: local row = mat*32 + jj  <->  global row mat*512 + j0 + jj
    for (int i = tid; i < 128 * 16; i += 256) {
        int r = i >> 4, c = i & 15;
        int mat = r >> 5, jj = r & 31;
        const uint4* src = reinterpret_cast<const uint4*>(
            g_w1 + ((size_t)(mat * HH + j0 + jj)) * II);
        *reinterpret_cast<uint4*>(&S.W[r * P1_PITCH + c * 8]) = src[c];
    }
    __syncthreads();

    const int lane = tid & 31, warp = tid >> 5;
    const int g = lane >> 2, t = lane & 3;
    float acc[16][4];
#pragma unroll
    for (int nt = 0; nt < 16; nt++)
#pragma unroll
        for (int q = 0; q < 4; q++) acc[nt][q] = 0.f;

    const int ar0 = (warp * 16 + g) * P1_PITCH;
    const int ar1 = (warp * 16 + g + 8) * P1_PITCH;
#pragma unroll
    for (int ks = 0; ks < 8; ks++) {
        const int k0 = ks * 16 + 2 * t;
        unsigned a0 = *reinterpret_cast<unsigned*>(&S.A[ar0 + k0]);
        unsigned a1 = *reinterpret_cast<unsigned*>(&S.A[ar1 + k0]);
        unsigned a2 = *reinterpret_cast<unsigned*>(&S.A[ar0 + k0 + 8]);
        unsigned a3 = *reinterpret_cast<unsigned*>(&S.A[ar1 + k0 + 8]);
#pragma unroll
        for (int nt = 0; nt < 16; nt++) {
            unsigned b0 = *reinterpret_cast<unsigned*>(&S.W[(nt * 8 + g) * P1_PITCH + k0]);
            unsigned b1 = *reinterpret_cast<unsigned*>(&S.W[(nt * 8 + g) * P1_PITCH + k0 + 8]);
            mma16816(acc[nt], a0, a1, a2, a3, b0, b1);
        }
    }

    // epilogue: sens = (sw+bsw)*sigmoid(smu+bsm)*exp(min(ssig+bss,50)); tcx += btc
#pragma unroll
    for (int jb = 0; jb < 4; jb++) {
#pragma unroll
        for (int ri = 0; ri < 2; ri++) {
#pragma unroll
            for (int tt = 0; tt < 2; tt++) {
                int q = ri * 2 + tt;
                int jl = jb * 8 + 2 * t + tt;
                int jg = j0 + jl;
                float sw   = acc[0 * 4 + jb][q] + bsw[jg];
                float smu  = acc[1 * 4 + jb][q] + bsm[jg];
                float ssig = acc[2 * 4 + jb][q] + bss[jg];
                float tc   = acc[3 * 4 + jb][q] + btc[jg];
                float sig  = __fdividef(1.f, 1.f + __expf(-smu));
                float sens = sw * sig * __expf(fminf(ssig, 50.f));
                int ml = warp * 16 + g + ri * 8;
                S.sens[ml * 32 + jl] = __float2half(sens);
                S.tcx [ml * 32 + jl] = __float2half(tc);
            }
        }
    }
    __syncthreads();

    // coalesced write-out into (t, b, j) layout
    {
        int r = tid & 127;
        int m = m0 + r;
        int b = m >> 10, tm = m & 1023;
        size_t dst = ((size_t)(tm * 64 + b)) * HH + j0;
        if (tid < 128) {
            uint4* d = reinterpret_cast<uint4*>(g_sens + dst);
            const uint4* s = reinterpret_cast<const uint4*>(&S.sens[r * 32]);
            d[0] = s[0]; d[1] = s[1]; d[2] = s[2]; d[3] = s[3];
        } else {
            uint4* d = reinterpret_cast<uint4*>(g_tcx + dst);
            const uint4* s = reinterpret_cast<const uint4*>(&S.tcx[r * 32]);
            d[0] = s[0]; d[1] = s[1]; d[2] = s[2]; d[3] = s[3];
        }
    }
}

// ---------------- phase 2: the recurrence (persistent, grid-synced) ----------------
// 64 CTAs; CTA c owns hidden units j in [8c, 8c+8). Weights (32 x 512 fp16) resident in SMEM.
#define P2_PITCH 520   // 512 + 8 halves pad
struct P2Smem {
    __half W [32 * P2_PITCH];   // [mat*8 + jj][k]
    __half Hs[64 * P2_PITCH];   // full h_t, fp16
    __half sens[64 * 8];
    __half tcx [64 * 8];
    __half hn  [64 * 8];
    float  outs[64 * 8];
};

__global__ void __launch_bounds__(THR2, 1)
phase2_kernel(float* __restrict__ out,
              const float* __restrict__ biw, const float* __restrict__ bim,
              const float* __restrict__ bis) {
    extern __shared__ char smem_raw[];
    P2Smem& S = *reinterpret_cast<P2Smem*>(smem_raw);
    const int tid = threadIdx.x;
    const int cta = blockIdx.x;
    const int lane = tid & 31, warp = tid >> 5;
    const int g = lane >> 2, t = lane & 3;

    // preload weight slab once (32 rows x 1 KB)
    for (int i = tid; i < 32 * 64; i += THR2) {
        int r = i >> 6, c = i & 63;
        int mat = r >> 3, jj = r & 7;
        const uint4* src = reinterpret_cast<const uint4*>(
            g_w2 + ((size_t)(mat * HH + cta * 8 + jj)) * HH);
        *reinterpret_cast<uint4*>(&S.W[r * P2_PITCH + c * 8]) = src[c];
    }
    // per-thread biases (fixed j pair for the whole run)
    float biwv[2], bimv[2], bisv[2];
    {
        int jg = cta * 8 + 2 * t;
        biwv[0] = biw[jg]; biwv[1] = biw[jg + 1];
        bimv[0] = bim[jg]; bimv[1] = bim[jg + 1];
        bisv[0] = bis[jg]; bisv[1] = bis[jg + 1];
    }
    float h_master[4];
#pragma unroll
    for (int q = 0; q < 4; q++) h_master[q] = 1.0f;   // h0 = ones (fp32 master)

    unsigned gen_target = 0;
    const int ar0 = (warp * 16 + g) * P2_PITCH;
    const int ar1 = ar0 + 8 * P2_PITCH;

    for (int step = 0; step < TT; step++) {
        // broadcast-read full h_t into SMEM (64 x 512 fp16)
        const __half* hsrc = g_hbuf + (size_t)(step & 1) * BB * HH;
        for (int i = tid; i < 64 * 64; i += THR2) {
            int r = i >> 6, c = i & 63;
            *reinterpret_cast<uint4*>(&S.Hs[r * P2_PITCH + c * 8]) =
                *reinterpret_cast<const uint4*>(hsrc + r * HH + c * 8);
        }
        // stage this step's sensory / tcx slice (64 x 8 each)
        if (tid < 64) {
            *reinterpret_cast<uint4*>(&S.sens[tid * 8]) =
                *reinterpret_cast<const uint4*>(g_sens + ((size_t)(step * 64 + tid)) * HH + cta * 8);
        } else {
            int r = tid - 64;
            *reinterpret_cast<uint4*>(&S.tcx[r * 8]) =
                *reinterpret_cast<const uint4*>(g_tcx + ((size_t)(step * 64 + r)) * HH + cta * 8);
        }
        __syncthreads();

        // fused 4-matrix GEMM: (64 x 512) x (512 x 32)
        float acc[4][4];
#pragma unroll
        for (int mt = 0; mt < 4; mt++)
#pragma unroll
            for (int q = 0; q < 4; q++) acc[mt][q] = 0.f;

#pragma unroll 4
        for (int ks = 0; ks < 32; ks++) {
            const int k0 = ks * 16 + 2 * t;
            unsigned a0 = *reinterpret_cast<unsigned*>(&S.Hs[ar0 + k0]);
            unsigned a1 = *reinterpret_cast<unsigned*>(&S.Hs[ar1 + k0]);
            unsigned a2 = *reinterpret_cast<unsigned*>(&S.Hs[ar0 + k0 + 8]);
            unsigned a3 = *reinterpret_cast<unsigned*>(&S.Hs[ar1 + k0 + 8]);
#pragma unroll
            for (int mt = 0; mt < 4; mt++) {
                unsigned b0 = *reinterpret_cast<unsigned*>(&S.W[(mt * 8 + g) * P2_PITCH + k0]);
                unsigned b1 = *reinterpret_cast<unsigned*>(&S.W[(mt * 8 + g) * P2_PITCH + k0 + 8]);
                mma16816(acc[mt], a0, a1, a2, a3, b0, b1);
            }
        }

        // epilogue: liquid time-constant update, fp32 master in registers
#pragma unroll
        for (int ri = 0; ri < 2; ri++) {
#pragma unroll
            for (int tt = 0; tt < 2; tt++) {
                int q  = ri * 2 + tt;
                int bl = warp * 16 + g + ri * 8;
                int jl = 2 * t + tt;
                float sens = __half2float(S.sens[bl * 8 + jl]);
                float tc0  = __half2float(S.tcx [bl * 8 + jl]);
                float ytc = acc[0][q];
                float yw  = acc[1][q] + biwv[tt];
                float ym  = acc[2][q] + bimv[tt];
                float ys  = acc[3][q] + bisv[tt];
                float xs  = tc0 + ytc;
                float sp  = (xs > 20.f) ? xs : __logf(1.f + __expf(xs));
                float tau = sp + 0.1f;
                float sig = __fdividef(1.f, 1.f + __expf(-ym));
                float inter = yw * sig * __expf(fminf(ys, 50.f));
                float hm = h_master[q];
                float hn = hm + DT_C * __fdividef(sens + inter - hm, fmaxf(tau, EPS_C));
                h_master[q] = hn;
                S.hn  [bl * 8 + jl] = __float2half(hn);
                S.outs[bl * 8 + jl] = hn;
            }
        }
        __syncthreads();

        // publish h_{t+1} (other buffer) + write output slice
        if (tid < 64) {
            __half* hd = g_hbuf + (size_t)((step + 1) & 1) * BB * HH + (size_t)tid * HH + cta * 8;
            *reinterpret_cast<uint4*>(hd) = *reinterpret_cast<const uint4*>(&S.hn[tid * 8]);
        } else {
            int r = tid - 64;
            float* od = out + (size_t)r * TT * HH + (size_t)step * HH + cta * 8;
            const float* s = &S.outs[r * 8];
            *reinterpret_cast<uint4*>(od)     = *reinterpret_cast<const uint4*>(s);
            *reinterpret_cast<uint4*>(od + 4) = *reinterpret_cast<const uint4*>(s + 4);
        }

        // grid barrier (all 64 CTAs co-resident: 1 CTA/SM)
        __syncthreads();
        gen_target++;
        if (tid == 0) {
            __threadfence();
            unsigned a = atomicAdd(&g_bar, 1);
            if (a == NCTA2 - 1) {
                atomicExch(&g_bar, 0);
                __threadfence();
                g_gen = gen_target;
            } else {
                while (g_gen < gen_target) { }
            }
            __threadfence();
        }
        __syncthreads();
    }
}

// ---------------- launch ----------------
extern "C" void kernel_launch(void* const* d_in, const int* in_sizes, int n_in,
                              void* d_out, int out_size) {
    const float* x    = (const float*)d_in[0];
    const float* Wsw  = (const float*)d_in[1];
    const float* bsw  = (const float*)d_in[2];
    const float* Wsm  = (const float*)d_in[3];
    const float* bsm  = (const float*)d_in[4];
    const float* Wss  = (const float*)d_in[5];
    const float* bss  = (const float*)d_in[6];
    const float* Wiw  = (const float*)d_in[7];
    const float* biw  = (const float*)d_in[8];
    const float* Wim  = (const float*)d_in[9];
    const float* bim  = (const float*)d_in[10];
    const float* Wis  = (const float*)d_in[11];
    const float* bis  = (const float*)d_in[12];
    const float* Wtcx = (const float*)d_in[13];
    const float* Wtch = (const float*)d_in[14];
    const float* btc  = (const float*)d_in[15];
    float* out = (float*)d_out;

    cudaFuncSetAttribute(phase1_kernel, cudaFuncAttributeMaxDynamicSharedMemorySize,
                         (int)sizeof(P1Smem));
    cudaFuncSetAttribute(phase2_kernel, cudaFuncAttributeMaxDynamicSharedMemorySize,
                         (int)sizeof(P2Smem));

    long long nprep = (long long)BB * TT * II;
    prep_kernel<<<(int)((nprep + 255) / 256), 256>>>(x, Wsw, Wsm, Wss, Wtcx, Wtch, Wiw, Wim, Wis);

    dim3 g1(512, 16);   // 65536/128 m-tiles, 512/32 j-tiles
    phase1_kernel<<<g1, 256, sizeof(P1Smem)>>>(bsw, bsm, bss, btc);

    phase2_kernel<<<NCTA2, THR2, sizeof(P2Smem)>>>(out, biw, bim, bis);
}

// round 2
// speedup vs baseline: 1.1106x; 1.1106x over previous
#include <cuda_runtime.h>
#include <cuda_fp16.h>

#define BB 64
#define TT 1024
#define II 128
#define HH 512

static constexpr int   NCTA2 = 64;   // phase-2 CTAs (1 per SM, co-resident)
static constexpr int   THR2  = 256;  // 8 warps: 2 k-halves x 4 m-tiles
static constexpr float DT_C  = 0.1f;
static constexpr float EPS_C = 1e-8f;

// ---------------- scratch (device globals: no allocation allowed) ----------------
__device__ __align__(16) __half g_xh  [BB * TT * II];   // x in fp16
__device__ __align__(16) __half g_w1  [4 * HH * II];    // [mat][j][k] (Wsw,Wsm,Wss,Wtcx)
__device__ __align__(16) __half g_w2  [4 * HH * HH];    // [mat][j][k] (Wtch,Wiw,Wim,Wis)
__device__ __align__(16) __half g_sens[TT * BB * HH];   // sensory (t,b,j)
__device__ __align__(16) __half g_tcx [TT * BB * HH];   // tcx+btc (t,b,j)
__device__ __align__(16) __half g_hbuf[2 * BB * HH];    // ping-pong h (fp16 broadcast)
__device__ unsigned          g_bar;
__device__ volatile unsigned g_gen;

// ---------------- PTX helpers ----------------
__device__ __forceinline__ void mma16816(float* c,
                                         unsigned a0, unsigned a1, unsigned a2, unsigned a3,
                                         unsigned b0, unsigned b1) {
    asm volatile(
        "mma.sync.aligned.m16n8k16.row.col.f32.f16.f16.f32 "
        "{%0,%1,%2,%3},{%4,%5,%6,%7},{%8,%9},{%0,%1,%2,%3};\n"
        : "+f"(c[0]), "+f"(c[1]), "+f"(c[2]), "+f"(c[3])
        : "r"(a0), "r"(a1), "r"(a2), "r"(a3), "r"(b0), "r"(b1));
}
__device__ __forceinline__ unsigned smem_u32(const void* p) {
    return (unsigned)__cvta_generic_to_shared(p);
}
__device__ __forceinline__ void cp16(unsigned sa, const void* ga) {
    asm volatile("cp.async.cg.shared.global [%0], [%1], 16;\n" :: "r"(sa), "l"(ga));
}
#define CP_COMMIT() asm volatile("cp.async.commit_group;\n" ::: "memory")
#define CP_WAIT(n)  asm volatile("cp.async.wait_group %0;\n" :: "n"(n) : "memory")
__device__ __forceinline__ void ldsm4(unsigned& r0, unsigned& r1, unsigned& r2, unsigned& r3,
                                      unsigned addr) {
    asm volatile("ldmatrix.sync.aligned.m8n8.x4.shared.b16 {%0,%1,%2,%3},[%4];\n"
                 : "=r"(r0), "=r"(r1), "=r"(r2), "=r"(r3) : "r"(addr));
}

// ---------------- prep: fp16 conversion, weight packing, state init ----------------
__global__ void prep_kernel(const float* __restrict__ x,
                            const float* __restrict__ Wsw, const float* __restrict__ Wsm,
                            const float* __restrict__ Wss, const float* __restrict__ Wtcx,
                            const float* __restrict__ Wtch, const float* __restrict__ Wiw,
                            const float* __restrict__ Wim, const float* __restrict__ Wis) {
    long long i = (long long)blockIdx.x * blockDim.x + threadIdx.x;
    if (i < (long long)BB * TT * II) g_xh[i] = __float2half(x[i]);
    if (i < 4 * HH * II) {
        int mat = (int)(i / (HH * II)); int rem = (int)(i % (HH * II));
        const float* W = (mat == 0) ? Wsw : (mat == 1) ? Wsm : (mat == 2) ? Wss : Wtcx;
        g_w1[i] = __float2half(W[rem]);
    }
    if (i < 4 * HH * HH) {
        int mat = (int)(i / (HH * HH)); int rem = (int)(i % (HH * HH));
        const float* W = (mat == 0) ? Wtch : (mat == 1) ? Wiw : (mat == 2) ? Wim : Wis;
        g_w2[i] = __float2half(W[rem]);
    }
    if (i < BB * HH) g_hbuf[i] = __float2half(1.0f);   // h0 = ones, buffer 0
    if (i == 0) { g_bar = 0; g_gen = 0; }
}

// ---------------- phase 1: input projections -> sensory & tcx ----------------
#define P1_PITCH 136
struct P1Smem {
    __half A[128 * P1_PITCH];
    __half W[128 * P1_PITCH];
    __half sens[128 * 32];
    __half tcx[128 * 32];
};

__global__ void phase1_kernel(const float* __restrict__ bsw, const float* __restrict__ bsm,
                              const float* __restrict__ bss, const float* __restrict__ btc) {
    extern __shared__ char smem_raw[];
    P1Smem& S = *reinterpret_cast<P1Smem*>(smem_raw);
    const int tid = threadIdx.x;
    const int m0 = blockIdx.x * 128;
    const int j0 = blockIdx.y * 32;

    {
        const uint4* src = reinterpret_cast<const uint4*>(g_xh + (size_t)m0 * II);
        for (int i = tid; i < 128 * 16; i += 256) {
            int r = i >> 4, c = i & 15;
            *reinterpret_cast<uint4*>(&S.A[r * P1_PITCH + c * 8]) = src[r * 16 + c];
        }
    }
    for (int i = tid; i < 128 * 16; i += 256) {
        int r = i >> 4, c = i & 15;
        int mat = r >> 5, jj = r & 31;
        const uint4* src = reinterpret_cast<const uint4*>(
            g_w1 + ((size_t)(mat * HH + j0 + jj)) * II);
        *reinterpret_cast<uint4*>(&S.W[r * P1_PITCH + c * 8]) = src[c];
    }
    __syncthreads();

    const int lane = tid & 31, warp = tid >> 5;
    const int g = lane >> 2, t = lane & 3;
    float acc[16][4];
#pragma unroll
    for (int nt = 0; nt < 16; nt++)
#pragma unroll
        for (int q = 0; q < 4; q++) acc[nt][q] = 0.f;

    const int ar0 = (warp * 16 + g) * P1_PITCH;
    const int ar1 = (warp * 16 + g + 8) * P1_PITCH;
#pragma unroll
    for (int ks = 0; ks < 8; ks++) {
        const int k0 = ks * 16 + 2 * t;
        unsigned a0 = *reinterpret_cast<unsigned*>(&S.A[ar0 + k0]);
        unsigned a1 = *reinterpret_cast<unsigned*>(&S.A[ar1 + k0]);
        unsigned a2 = *reinterpret_cast<unsigned*>(&S.A[ar0 + k0 + 8]);
        unsigned a3 = *reinterpret_cast<unsigned*>(&S.A[ar1 + k0 + 8]);
#pragma unroll
        for (int nt = 0; nt < 16; nt++) {
            unsigned b0 = *reinterpret_cast<unsigned*>(&S.W[(nt * 8 + g) * P1_PITCH + k0]);
            unsigned b1 = *reinterpret_cast<unsigned*>(&S.W[(nt * 8 + g) * P1_PITCH + k0 + 8]);
            mma16816(acc[nt], a0, a1, a2, a3, b0, b1);
        }
    }

#pragma unroll
    for (int jb = 0; jb < 4; jb++) {
#pragma unroll
        for (int ri = 0; ri < 2; ri++) {
#pragma unroll
            for (int tt = 0; tt < 2; tt++) {
                int q = ri * 2 + tt;
                int jl = jb * 8 + 2 * t + tt;
                int jg = j0 + jl;
                float sw   = acc[0 * 4 + jb][q] + bsw[jg];
                float smu  = acc[1 * 4 + jb][q] + bsm[jg];
                float ssig = acc[2 * 4 + jb][q] + bss[jg];
                float tc   = acc[3 * 4 + jb][q] + btc[jg];
                float sig  = __fdividef(1.f, 1.f + __expf(-smu));
                float sens = sw * sig * __expf(fminf(ssig, 50.f));
                int ml = warp * 16 + g + ri * 8;
                S.sens[ml * 32 + jl] = __float2half(sens);
                S.tcx [ml * 32 + jl] = __float2half(tc);
            }
        }
    }
    __syncthreads();

    {
        int r = tid & 127;
        int m = m0 + r;
        int b = m >> 10, tm = m & 1023;
        size_t dst = ((size_t)(tm * 64 + b)) * HH + j0;
        if (tid < 128) {
            uint4* d = reinterpret_cast<uint4*>(g_sens + dst);
            const uint4* s = reinterpret_cast<const uint4*>(&S.sens[r * 32]);
            d[0] = s[0]; d[1] = s[1]; d[2] = s[2]; d[3] = s[3];
        } else {
            uint4* d = reinterpret_cast<uint4*>(g_tcx + dst);
            const uint4* s = reinterpret_cast<const uint4*>(&S.tcx[r * 32]);
            d[0] = s[0]; d[1] = s[1]; d[2] = s[2]; d[3] = s[3];
        }
    }
}

// ---------------- phase 2: the recurrence (persistent, grid-synced) ----------------
// 64 CTAs; CTA c owns hidden units [8c, 8c+8). 8 warps: warp = kh*4 + mw.
//   kh (0/1): k-range [kh*256, kh*256+256)   mw (0..3): m-rows [mw*16, mw*16+16)
// Weight B-fragments live in REGISTERS for all 1024 steps (128 regs/thread).
#define P2_PITCH 520   // 512 + 8 halves pad (conflict-free LDSM, 16B-aligned rows)
struct P2Smem {
    __half W [32 * P2_PITCH];   // [mat*8 + jj][k]  (staging for reg preload)
    __half Hs[64 * P2_PITCH];   // full h_t, fp16
    __half sens[64 * 8];
    __half tcx [64 * 8];
    __half hn  [64 * 8];
    float  outs[64 * 8];
    float  rbuf[4 * 16 * 32];   // split-K partials: [mw][idx][lane]
};

__global__ void __launch_bounds__(THR2, 1)
phase2_kernel(float* __restrict__ out,
              const float* __restrict__ biw, const float* __restrict__ bim,
              const float* __restrict__ bis) {
    extern __shared__ char smem_raw[];
    P2Smem& S = *reinterpret_cast<P2Smem*>(smem_raw);
    const int tid  = threadIdx.x;
    const int cta  = blockIdx.x;
    const int lane = tid & 31, warp = tid >> 5;
    const int mw = warp & 3, kh = warp >> 2;
    const int g = lane >> 2, t = lane & 3;

    // ---- stage weight slab (32 x 512 fp16) via cp.async, then preload B frags to regs ----
    for (int i = tid; i < 32 * 64; i += THR2) {
        int r = i >> 6, c = i & 63;
        int mat = r >> 3, jj = r & 7;
        cp16(smem_u32(&S.W[r * P2_PITCH + c * 8]),
             g_w2 + ((size_t)(mat * HH + cta * 8 + jj)) * HH + c * 8);
    }
    CP_COMMIT(); CP_WAIT(0);
    __syncthreads();

    unsigned bfr[16][4][2];   // [ks within my k-half][mat][2]
#pragma unroll
    for (int ks = 0; ks < 16; ks++) {
        const int k0 = kh * 256 + ks * 16 + 2 * t;
#pragma unroll
        for (int mt = 0; mt < 4; mt++) {
            bfr[ks][mt][0] = *reinterpret_cast<unsigned*>(&S.W[(mt * 8 + g) * P2_PITCH + k0]);
            bfr[ks][mt][1] = *reinterpret_cast<unsigned*>(&S.W[(mt * 8 + g) * P2_PITCH + k0 + 8]);
        }
    }

    // per-thread biases (epilogue threads only use these; loading everywhere is harmless)
    float biwv[2], bimv[2], bisv[2];
    {
        int jg = cta * 8 + 2 * t;
        biwv[0] = biw[jg]; biwv[1] = biw[jg + 1];
        bimv[0] = bim[jg]; bimv[1] = bim[jg + 1];
        bisv[0] = bis[jg]; bisv[1] = bis[jg + 1];
    }
    float h_master[4];
#pragma unroll
    for (int q = 0; q < 4; q++) h_master[q] = 1.0f;

    // ldmatrix address: row = mw*16 + (lane&15), col block = kh*256 + (lane>>4)*8
    const unsigned aAddrBase =
        smem_u32(&S.Hs[(mw * 16 + (lane & 15)) * P2_PITCH + kh * 256 + ((lane >> 4) * 8)]);

    unsigned gen_target = 0;

    for (int step = 0; step < TT; step++) {
        // ---- async stage h_t (64x512 fp16) + this step's sens/tcx slices ----
        const __half* hsrc = g_hbuf + (size_t)(step & 1) * BB * HH;
        for (int i = tid; i < 64 * 64; i += THR2) {
            int r = i >> 6, c = i & 63;
            cp16(smem_u32(&S.Hs[r * P2_PITCH + c * 8]), hsrc + r * HH + c * 8);
        }
        CP_COMMIT();                       // group: Hs
        if (tid < 64) {
            cp16(smem_u32(&S.sens[tid * 8]),
                 g_sens + ((size_t)(step * 64 + tid)) * HH + cta * 8);
        } else if (tid < 128) {
            int r = tid - 64;
            cp16(smem_u32(&S.tcx[r * 8]),
                 g_tcx + ((size_t)(step * 64 + r)) * HH + cta * 8);
        }
        CP_COMMIT();                       // group: sens/tcx
        CP_WAIT(1);                        // Hs complete (sens may still fly)
        __syncthreads();

        // ---- fused 4-matrix split-K GEMM: (64 x 512) x (512 x 32) ----
        float acc[4][4];
#pragma unroll
        for (int mt = 0; mt < 4; mt++)
#pragma unroll
            for (int q = 0; q < 4; q++) acc[mt][q] = 0.f;

#pragma unroll
        for (int ks = 0; ks < 16; ks++) {
            unsigned a0, a1, a2, a3;
            ldsm4(a0, a1, a2, a3, aAddrBase + ks * 32);
#pragma unroll
            for (int mt = 0; mt < 4; mt++)
                mma16816(acc[mt], a0, a1, a2, a3, bfr[ks][mt][0], bfr[ks][mt][1]);
        }

        CP_WAIT(0);                        // sens/tcx complete
        // ---- split-K reduction: kh=1 warps publish partials ----
        if (kh == 1) {
#pragma unroll
            for (int mt = 0; mt < 4; mt++)
#pragma unroll
                for (int q = 0; q < 4; q++)
                    S.rbuf[(mw * 16 + mt * 4 + q) * 32 + lane] = acc[mt][q];
        }
        __syncthreads();

        if (kh == 0) {
#pragma unroll
            for (int mt = 0; mt < 4; mt++)
#pragma unroll
                for (int q = 0; q < 4; q++)
                    acc[mt][q] += S.rbuf[(mw * 16 + mt * 4 + q) * 32 + lane];

            // ---- epilogue: liquid time-constant update (fp32 master in regs) ----
#pragma unroll
            for (int ri = 0; ri < 2; ri++) {
#pragma unroll
                for (int tt = 0; tt < 2; tt++) {
                    int q  = ri * 2 + tt;
                    int bl = mw * 16 + g + ri * 8;
                    int jl = 2 * t + tt;
                    float sens = __half2float(S.sens[bl * 8 + jl]);
                    float tc0  = __half2float(S.tcx [bl * 8 + jl]);
                    float ytc = acc[0][q];
                    float yw  = acc[1][q] + biwv[tt];
                    float ym  = acc[2][q] + bimv[tt];
                    float ys  = acc[3][q] + bisv[tt];
                    float xs  = tc0 + ytc;
                    float sp  = (xs > 20.f) ? xs : __logf(1.f + __expf(xs));
                    float tau = sp + 0.1f;
                    float sig = __fdividef(1.f, 1.f + __expf(-ym));
                    float inter = yw * sig * __expf(fminf(ys, 50.f));
                    float hm = h_master[q];
                    float hn = hm + DT_C * __fdividef(sens + inter - hm, fmaxf(tau, EPS_C));
                    h_master[q] = hn;
                    S.hn  [bl * 8 + jl] = __float2half(hn);
                    S.outs[bl * 8 + jl] = hn;
                }
            }
        }
        __syncthreads();

        // ---- publish h_{t+1} + write output slice ----
        if (tid < 64) {
            __half* hd = g_hbuf + (size_t)((step + 1) & 1) * BB * HH
                       + (size_t)tid * HH + cta * 8;
            *reinterpret_cast<uint4*>(hd) = *reinterpret_cast<const uint4*>(&S.hn[tid * 8]);
        } else if (tid < 192) {
            int u = tid - 64;
            int r = u >> 1, part = u & 1;
            float* od = out + (size_t)r * TT * HH + (size_t)step * HH + cta * 8 + part * 4;
            *reinterpret_cast<uint4*>(od) =
                *reinterpret_cast<const uint4*>(&S.outs[r * 8 + part * 4]);
        }

        // ---- grid barrier (64 co-resident CTAs) ----
        __threadfence();   // release: make this CTA's STGs globally visible
        __syncthreads();
        gen_target++;
        if (tid == 0) {
            unsigned a = atomicAdd(&g_bar, 1);
            if (a == NCTA2 - 1) {
                atomicExch(&g_bar, 0);
                __threadfence();
                g_gen = gen_target;
            } else {
                while (g_gen < gen_target) { }
            }
            __threadfence();   // acquire
        }
        __syncthreads();
    }
}

// ---------------- launch ----------------
extern "C" void kernel_launch(void* const* d_in, const int* in_sizes, int n_in,
                              void* d_out, int out_size) {
    const float* x    = (const float*)d_in[0];
    const float* Wsw  = (const float*)d_in[1];
    const float* bsw  = (const float*)d_in[2];
    const float* Wsm  = (const float*)d_in[3];
    const float* bsm  = (const float*)d_in[4];
    const float* Wss  = (const float*)d_in[5];
    const float* bss  = (const float*)d_in[6];
    const float* Wiw  = (const float*)d_in[7];
    const float* biw  = (const float*)d_in[8];
    const float* Wim  = (const float*)d_in[9];
    const float* bim  = (const float*)d_in[10];
    const float* Wis  = (const float*)d_in[11];
    const float* bis  = (const float*)d_in[12];
    const float* Wtcx = (const float*)d_in[13];
    const float* Wtch = (const float*)d_in[14];
    const float* btc  = (const float*)d_in[15];
    float* out = (float*)d_out;

    cudaFuncSetAttribute(phase1_kernel, cudaFuncAttributeMaxDynamicSharedMemorySize,
                         (int)sizeof(P1Smem));
    cudaFuncSetAttribute(phase2_kernel, cudaFuncAttributeMaxDynamicSharedMemorySize,
                         (int)sizeof(P2Smem));

    long long nprep = (long long)BB * TT * II;
    prep_kernel<<<(int)((nprep + 255) / 256), 256>>>(x, Wsw, Wsm, Wss, Wtcx, Wtch, Wiw, Wim, Wis);

    dim3 g1(512, 16);
    phase1_kernel<<<g1, 256, sizeof(P1Smem)>>>(bsw, bsm, bss, btc);

    phase2_kernel<<<NCTA2, THR2, sizeof(P2Smem)>>>(out, biw, bim, bis);
}

// round 5
// speedup vs baseline: 1.8232x; 1.6417x over previous
#include <cuda_runtime.h>
#include <cuda_fp16.h>
#include <cstdint>

#define BB 64
#define TT 1024
#define II 128
#define HH 512

static constexpr int   NCTA2 = 64;
static constexpr int   THR2  = 256;   // 8 warps: 2 k-halves x 4 m-tiles
static constexpr float DT_C  = 0.1f;
static constexpr float EPS_C = 1e-8f;

// ---------------- device scratch ----------------
// g_st: per step t, per CTA jb, per batch b: 8 sens + 8 tcx halves (contiguous 2KB per (t,jb))
__device__ __align__(16)  __half g_st[(size_t)TT * 64 * 64 * 16];
// g_hbuf: ping-pong h, SWIZZLED image: row b (1024B), 16B chunk c stored at chunk (c ^ (b&7))
__device__ __align__(128) __half g_hbuf[2 * BB * HH];    // 2 x 64 KB
__device__ unsigned g_bar;   // monotonic arrival counter (reset by phase1)
__device__ unsigned g_gen;   // generation (reset by phase1)

// ---------------- helpers ----------------
__device__ __forceinline__ unsigned smem_u32(const void* p) {
    return (unsigned)__cvta_generic_to_shared(p);
}
__device__ __forceinline__ void mma16816(float* c,
                                         unsigned a0, unsigned a1, unsigned a2, unsigned a3,
                                         unsigned b0, unsigned b1) {
    asm volatile(
        "mma.sync.aligned.m16n8k16.row.col.f32.f16.f16.f32 "
        "{%0,%1,%2,%3},{%4,%5,%6,%7},{%8,%9},{%0,%1,%2,%3};\n"
        : "+f"(c[0]), "+f"(c[1]), "+f"(c[2]), "+f"(c[3])
        : "r"(a0), "r"(a1), "r"(a2), "r"(a3), "r"(b0), "r"(b1));
}
__device__ __forceinline__ void ldsm4(unsigned& r0, unsigned& r1, unsigned& r2, unsigned& r3,
                                      unsigned addr) {
    asm volatile("ldmatrix.sync.aligned.m8n8.x4.shared.b16 {%0,%1,%2,%3},[%4];\n"
                 : "=r"(r0), "=r"(r1), "=r"(r2), "=r"(r3) : "r"(addr));
}
__device__ __forceinline__ uint4 pack8f(float4 f0, float4 f1) {
    __half2 h0 = __floats2half2_rn(f0.x, f0.y), h1 = __floats2half2_rn(f0.z, f0.w);
    __half2 h2 = __floats2half2_rn(f1.x, f1.y), h3 = __floats2half2_rn(f1.z, f1.w);
    uint4 pv;
    pv.x = *reinterpret_cast<unsigned*>(&h0); pv.y = *reinterpret_cast<unsigned*>(&h1);
    pv.z = *reinterpret_cast<unsigned*>(&h2); pv.w = *reinterpret_cast<unsigned*>(&h3);
    return pv;
}
__device__ __forceinline__ void bulk_g2s(uint32_t dst, const void* src, uint32_t bytes,
                                         uint32_t mbar) {
    asm volatile(
        "cp.async.bulk.shared::cluster.global.mbarrier::complete_tx::bytes [%0], [%1], %2, [%3];\n"
        :: "r"(dst), "l"(src), "r"(bytes), "r"(mbar) : "memory");
}
#define MBAR_INIT(a, n) \
    asm volatile("mbarrier.init.shared.b64 [%0], %1;" :: "r"(a), "r"((unsigned)(n)) : "memory")
#define MBAR_EXPECT_TX(a, n) \
    asm volatile("mbarrier.arrive.expect_tx.shared.b64 _, [%0], %1;" :: "r"(a), "r"((unsigned)(n)) : "memory")
__device__ __forceinline__ void mbar_wait(uint32_t a, uint32_t parity) {
    asm volatile(
        "{\n\t.reg .pred P1;\n\t"
        "WAIT_LOOP_%=:\n\t"
        "mbarrier.try_wait.parity.acquire.cta.shared::cta.b64 P1, [%0], %1, 0x989680;\n\t"
        "@P1 bra.uni WAIT_DONE_%=;\n\t"
        "bra.uni WAIT_LOOP_%=;\n\t"
        "WAIT_DONE_%=:\n\t}"
        :: "r"(a), "r"(parity) : "memory");
}
#define FENCE_PROXY_ASYNC() asm volatile("fence.proxy.async.shared::cta;" ::: "memory")

// ---------------- phase 1: input projections -> g_st ----------------
#define P1_PITCH 136
struct P1Smem {
    __half A[128 * P1_PITCH];
    __half W[128 * P1_PITCH];
    __half sens[128 * 32];
    __half tcx[128 * 32];
};

__global__ void phase1_kernel(const float* __restrict__ x,
                              const float* __restrict__ Wsw, const float* __restrict__ Wsm,
                              const float* __restrict__ Wss, const float* __restrict__ Wtcx,
                              const float* __restrict__ bsw, const float* __restrict__ bsm,
                              const float* __restrict__ bss, const float* __restrict__ btc) {
    extern __shared__ char smem_raw[];
    P1Smem& S = *reinterpret_cast<P1Smem*>(smem_raw);
    const int tid = threadIdx.x;
    const int m0 = blockIdx.x * 128;
    const int j0 = blockIdx.y * 32;

    if (blockIdx.x == 0 && blockIdx.y == 0 && tid == 0) { g_bar = 0; g_gen = 0; }

    for (int i = tid; i < 128 * 16; i += 256) {
        int r = i >> 4, c = i & 15;
        const float4* src = reinterpret_cast<const float4*>(x + (size_t)(m0 + r) * II + c * 8);
        *reinterpret_cast<uint4*>(&S.A[r * P1_PITCH + c * 8]) = pack8f(src[0], src[1]);
    }
    const float* Wp[4] = { Wsw, Wsm, Wss, Wtcx };
    for (int i = tid; i < 128 * 16; i += 256) {
        int r = i >> 4, c = i & 15;
        int mat = r >> 5, jj = r & 31;
        const float4* src = reinterpret_cast<const float4*>(Wp[mat] + (size_t)(j0 + jj) * II + c * 8);
        *reinterpret_cast<uint4*>(&S.W[r * P1_PITCH + c * 8]) = pack8f(src[0], src[1]);
    }
    __syncthreads();

    const int lane = tid & 31, warp = tid >> 5;
    const int g = lane >> 2, t = lane & 3;
    float acc[16][4];
#pragma unroll
    for (int nt = 0; nt < 16; nt++)
#pragma unroll
        for (int q = 0; q < 4; q++) acc[nt][q] = 0.f;

    const int ar0 = (warp * 16 + g) * P1_PITCH;
    const int ar1 = (warp * 16 + g + 8) * P1_PITCH;
#pragma unroll
    for (int ks = 0; ks < 8; ks++) {
        const int k0 = ks * 16 + 2 * t;
        unsigned a0 = *reinterpret_cast<unsigned*>(&S.A[ar0 + k0]);
        unsigned a1 = *reinterpret_cast<unsigned*>(&S.A[ar1 + k0]);
        unsigned a2 = *reinterpret_cast<unsigned*>(&S.A[ar0 + k0 + 8]);
        unsigned a3 = *reinterpret_cast<unsigned*>(&S.A[ar1 + k0 + 8]);
#pragma unroll
        for (int nt = 0; nt < 16; nt++) {
            unsigned b0 = *reinterpret_cast<unsigned*>(&S.W[(nt * 8 + g) * P1_PITCH + k0]);
            unsigned b1 = *reinterpret_cast<unsigned*>(&S.W[(nt * 8 + g) * P1_PITCH + k0 + 8]);
            mma16816(acc[nt], a0, a1, a2, a3, b0, b1);
        }
    }

#pragma unroll
    for (int jb = 0; jb < 4; jb++) {
#pragma unroll
        for (int ri = 0; ri < 2; ri++) {
#pragma unroll
            for (int tt = 0; tt < 2; tt++) {
                int q = ri * 2 + tt;
                int jl = jb * 8 + 2 * t + tt;
                int jg = j0 + jl;
                float sw   = acc[0 * 4 + jb][q] + bsw[jg];
                float smu  = acc[1 * 4 + jb][q] + bsm[jg];
                float ssig = acc[2 * 4 + jb][q] + bss[jg];
                float tc   = acc[3 * 4 + jb][q] + btc[jg];
                float sig  = __fdividef(1.f, 1.f + __expf(-smu));
                float sens = sw * sig * __expf(fminf(ssig, 50.f));
                int ml = warp * 16 + g + ri * 8;
                S.sens[ml * 32 + jl] = __float2half(sens);
                S.tcx [ml * 32 + jl] = __float2half(tc);
            }
        }
    }
    __syncthreads();

    // write-out: g_st[t][jb][b][0:8]=sens, [8:16]=tcx
    {
        int r = tid & 127;
        int m = m0 + r;
        int b = m >> 10, tm = m & 1023;
        int jb0 = j0 >> 3;
#pragma unroll
        for (int jbl = 0; jbl < 4; jbl++) {
            size_t dst = (((size_t)tm * 64 + jb0 + jbl) * 64 + b) * 16;
            if (tid < 128) {
                *reinterpret_cast<uint4*>(g_st + dst) =
                    *reinterpret_cast<const uint4*>(&S.sens[r * 32 + jbl * 8]);
            } else {
                *reinterpret_cast<uint4*>(g_st + dst + 8) =
                    *reinterpret_cast<const uint4*>(&S.tcx[r * 32 + jbl * 8]);
            }
        }
    }
}

// ---------------- phase 2: recurrence ----------------
// 64 CTAs; CTA c owns hidden units [8c, 8c+8). 8 warps: warp = kh*4 + mw.
// B-fragments in registers for all 1024 steps. h staged by ONE cp.async.bulk (64KB),
// conflict-free ldmatrix via 16B-chunk XOR swizzle baked into the gmem image.
#define WST_PITCH 520
struct P2Smem {
    __half  Hs[BB * HH];        // 64KB linear (row b: 1024B, chunks XOR-swizzled)
    __half  Wst[32 * WST_PITCH];// one-time weight staging
    __half  st[64 * 16];        // sens/tcx slice (bulk dst)
    __half  hn[64 * 8];
    float   outs[64 * 8];
    float   rbuf[4 * 16 * 32];  // split-K partials
    unsigned long long mbar[2]; // 8B aligned
};

__global__ void __launch_bounds__(THR2, 1)
phase2_kernel(float* __restrict__ out,
              const float* __restrict__ Wtch, const float* __restrict__ Wiw,
              const float* __restrict__ Wim,  const float* __restrict__ Wis,
              const float* __restrict__ biw, const float* __restrict__ bim,
              const float* __restrict__ bis) {
    extern __shared__ char smem_raw[];
    P2Smem& S = *reinterpret_cast<P2Smem*>(smem_raw);
    const int tid  = threadIdx.x;
    const int cta  = blockIdx.x;
    const int lane = tid & 31, warp = tid >> 5;
    const int mw = warp & 3, kh = warp >> 2;
    const int g = lane >> 2, t = lane & 3;

    const uint32_t MB_TMA = smem_u32(&S.mbar[0]);
    const uint32_t HSb    = smem_u32(&S.Hs[0]);

    // ---- one-time: stage weights (fp32 -> fp16, padded) and preload B frags ----
    const float* Wp[4] = { Wtch, Wiw, Wim, Wis };
    for (int i = tid; i < 32 * 64; i += THR2) {
        int r = i >> 6, c8 = (i & 63) * 8;
        int mat = r >> 3, jj = r & 7;
        const float4* src = reinterpret_cast<const float4*>(
            Wp[mat] + (size_t)(cta * 8 + jj) * HH + c8);
        *reinterpret_cast<uint4*>(&S.Wst[r * WST_PITCH + c8]) = pack8f(src[0], src[1]);
    }
    // init Hs = ones (h0)
    {
        uint4 ones = make_uint4(0x3C003C00u, 0x3C003C00u, 0x3C003C00u, 0x3C003C00u);
        for (int i = tid; i < BB * HH / 8; i += THR2)
            *reinterpret_cast<uint4*>(&S.Hs[i * 8]) = ones;
    }
    if (tid == 0) MBAR_INIT(MB_TMA, 1);
    __syncthreads();

    unsigned bfr[16][4][2];   // [ks in my k-half][mat][2]
#pragma unroll
    for (int ks = 0; ks < 16; ks++) {
        const int k0 = kh * 256 + ks * 16 + 2 * t;
#pragma unroll
        for (int mt = 0; mt < 4; mt++) {
            bfr[ks][mt][0] = *reinterpret_cast<unsigned*>(&S.Wst[(mt * 8 + g) * WST_PITCH + k0]);
            bfr[ks][mt][1] = *reinterpret_cast<unsigned*>(&S.Wst[(mt * 8 + g) * WST_PITCH + k0 + 8]);
        }
    }

    float biwv[2], bimv[2], bisv[2];
    {
        int jg = cta * 8 + 2 * t;
        biwv[0] = biw[jg]; biwv[1] = biw[jg + 1];
        bimv[0] = bim[jg]; bimv[1] = bim[jg + 1];
        bisv[0] = bis[jg]; bisv[1] = bis[jg + 1];
    }
    float h_master[4];
#pragma unroll
    for (int q = 0; q < 4; q++) h_master[q] = 1.0f;

    // ldmatrix addressing (swizzled): row = mw*16 + (lane&15)
    const int arow   = mw * 16 + (lane & 15);
    const unsigned rowbase = HSb + (unsigned)arow * 1024u;
    const unsigned rowx    = (unsigned)(arow & 7);
    const unsigned chunk0  = (unsigned)(kh * 32 + (lane >> 4));

    for (int s = 0; s < TT; s++) {
        // ---- stage h (bulk, s>0) + sens/tcx slice (bulk) ----
        if (tid == 0) {
            FENCE_PROXY_ASYNC();
            unsigned txn = (s > 0) ? (BB * HH * 2 + 2048) : 2048;
            MBAR_EXPECT_TX(MB_TMA, txn);
            if (s > 0) {
                const char* hsrc = (const char*)g_hbuf + (size_t)(s & 1) * (BB * HH * 2);
                bulk_g2s(HSb, hsrc, BB * HH * 2, MB_TMA);
            }
            bulk_g2s(smem_u32(&S.st[0]),
                     (const char*)g_st + (((size_t)s * 64 + cta) * 2048), 2048, MB_TMA);
        }
        mbar_wait(MB_TMA, (uint32_t)(s & 1));

        // ---- fused 4-matrix split-K GEMM: (64 x 512) x (512 x 32) ----
        float acc[4][4];
#pragma unroll
        for (int mt = 0; mt < 4; mt++)
#pragma unroll
            for (int q = 0; q < 4; q++) acc[mt][q] = 0.f;

#pragma unroll
        for (int ks = 0; ks < 16; ks++) {
            unsigned chunk = (chunk0 + (unsigned)(ks * 2)) ^ rowx;
            unsigned a0, a1, a2, a3;
            ldsm4(a0, a1, a2, a3, rowbase + chunk * 16u);
#pragma unroll
            for (int mt = 0; mt < 4; mt++)
                mma16816(acc[mt], a0, a1, a2, a3, bfr[ks][mt][0], bfr[ks][mt][1]);
        }

        // ---- split-K reduction ----
        if (kh == 1) {
#pragma unroll
            for (int mt = 0; mt < 4; mt++)
#pragma unroll
                for (int q = 0; q < 4; q++)
                    S.rbuf[(mw * 16 + mt * 4 + q) * 32 + lane] = acc[mt][q];
        }
        __syncthreads();

        if (kh == 0) {
#pragma unroll
            for (int mt = 0; mt < 4; mt++)
#pragma unroll
                for (int q = 0; q < 4; q++)
                    acc[mt][q] += S.rbuf[(mw * 16 + mt * 4 + q) * 32 + lane];

            // ---- epilogue ----
#pragma unroll
            for (int ri = 0; ri < 2; ri++) {
#pragma unroll
                for (int tt = 0; tt < 2; tt++) {
                    int q  = ri * 2 + tt;
                    int bl = mw * 16 + g + ri * 8;
                    int jl = 2 * t + tt;
                    float sens = __half2float(S.st[bl * 16 + jl]);
                    float tc0  = __half2float(S.st[bl * 16 + 8 + jl]);
                    float ytc = acc[0][q];
                    float yw  = acc[1][q] + biwv[tt];
                    float ym  = acc[2][q] + bimv[tt];
                    float ys  = acc[3][q] + bisv[tt];
                    float xs  = tc0 + ytc;
                    float sp  = (xs > 20.f) ? xs : __logf(1.f + __expf(xs));
                    float tau = sp + 0.1f;
                    float sig = __fdividef(1.f, 1.f + __expf(-ym));
                    float inter = yw * sig * __expf(fminf(ys, 50.f));
                    float hm = h_master[q];
                    float hn = hm + DT_C * __fdividef(sens + inter - hm, fmaxf(tau, EPS_C));
                    h_master[q] = hn;
                    S.hn  [bl * 8 + jl] = __float2half(hn);
                    S.outs[bl * 8 + jl] = hn;
                }
            }
        }
        __syncthreads();

        // ---- publish h_{s+1} (swizzled image, other buffer) + write out slice ----
        if (tid < 64) {
            unsigned swc = ((unsigned)cta) ^ ((unsigned)(tid & 7));
            char* hd = (char*)g_hbuf + (size_t)((s + 1) & 1) * (BB * HH * 2)
                     + (size_t)tid * 1024 + swc * 16u;
            *reinterpret_cast<uint4*>(hd) = *reinterpret_cast<const uint4*>(&S.hn[tid * 8]);
        } else if (tid < 192) {
            int u = tid - 64;
            int r = u >> 1, part = u & 1;
            float* od = out + (size_t)r * TT * HH + (size_t)s * HH + cta * 8 + part * 4;
            *reinterpret_cast<uint4*>(od) =
                *reinterpret_cast<const uint4*>(&S.outs[r * 8 + part * 4]);
        }

        if (s == TT - 1) break;

        // ---- grid barrier: release-atomic arrive + acquire spin ----
        __syncthreads();
        if (tid == 0) {
            unsigned old;
            asm volatile("atom.release.gpu.global.add.u32 %0, [%1], %2;"
                         : "=r"(old) : "l"(&g_bar), "r"(1u) : "memory");
            if (old == (unsigned)(s * NCTA2 + NCTA2 - 1)) {
                asm volatile("st.release.gpu.global.u32 [%0], %1;"
                             :: "l"(&g_gen), "r"((unsigned)(s + 1)) : "memory");
            } else {
                unsigned v;
                do {
                    asm volatile("ld.acquire.gpu.global.u32 %0, [%1];"
                                 : "=r"(v) : "l"(&g_gen) : "memory");
                } while (v <= (unsigned)s);
            }
        }
        __syncthreads();
    }
}

// ---------------- launch ----------------
extern "C" void kernel_launch(void* const* d_in, const int* in_sizes, int n_in,
                              void* d_out, int out_size) {
    const float* x    = (const float*)d_in[0];
    const float* Wsw  = (const float*)d_in[1];
    const float* bsw  = (const float*)d_in[2];
    const float* Wsm  = (const float*)d_in[3];
    const float* bsm  = (const float*)d_in[4];
    const float* Wss  = (const float*)d_in[5];
    const float* bss  = (const float*)d_in[6];
    const float* Wiw  = (const float*)d_in[7];
    const float* biw  = (const float*)d_in[8];
    const float* Wim  = (const float*)d_in[9];
    const float* bim  = (const float*)d_in[10];
    const float* Wis  = (const float*)d_in[11];
    const float* bis  = (const float*)d_in[12];
    const float* Wtcx = (const float*)d_in[13];
    const float* Wtch = (const float*)d_in[14];
    const float* btc  = (const float*)d_in[15];
    float* out = (float*)d_out;

    cudaFuncSetAttribute(phase1_kernel, cudaFuncAttributeMaxDynamicSharedMemorySize,
                         (int)sizeof(P1Smem));
    cudaFuncSetAttribute(phase2_kernel, cudaFuncAttributeMaxDynamicSharedMemorySize,
                         (int)sizeof(P2Smem));

    dim3 g1(512, 16);
    phase1_kernel<<<g1, 256, sizeof(P1Smem)>>>(x, Wsw, Wsm, Wss, Wtcx, bsw, bsm, bss, btc);

    phase2_kernel<<<NCTA2, THR2, sizeof(P2Smem)>>>(out, Wtch, Wiw, Wim, Wis, biw, bim, bis);
}